// round 8
// baseline (speedup 1.0000x reference)
#include <cuda_runtime.h>

#define BH        64
#define SEQ       16384
#define DV        64
#define RB        256                       // reducer blocks (bids 0..RB-1)
#define NBLK      1184
#define PST       68                        // partial stride in floats (272B, 16B aligned)
#define TILE_ROWS 256
#define NTILES    (BH * (SEQ / TILE_ROWS))  // 4096

struct SyncState { int cnt[BH]; int ready[BH]; int tile; };
__device__ SyncState g_sync;
__device__ __align__(16) float g_part[BH * RB * PST];
__device__ __align__(16) float g_coef[BH * DV];

__global__ __launch_bounds__(256) void fused_kernel(
    const float* __restrict__ Q,
    const float* __restrict__ K,
    const float* __restrict__ V,
    float* __restrict__ out)
{
    const int b    = blockIdx.x;
    const int tid  = threadIdx.x;
    const int eg   = tid & 15;
    const int rg   = tid >> 4;
    const int lane = tid & 31;
    const int warp = tid >> 5;

    __shared__ float4 sv[8][16];     // per-warp partial ktv; reused as finalize scratch
    __shared__ float2 sn[8];
    __shared__ float  s_k2, s_q2;
    __shared__ int    s_flag;
    __shared__ int    s_tile;

    // ------------------------------------------------------------------
    // Phase A (blocks 0..RB-1): reduce 64-row slice of every bh, in bh order.
    // ------------------------------------------------------------------
    if (b < RB) {
        const int R0 = b * 64;
        for (int bh = 0; bh < BH; bh++) {
            const float*  Kbh = K + (size_t)bh * SEQ;
            const float*  Qbh = Q + (size_t)bh * SEQ;
            const float4* V4  = (const float4*)V + (size_t)bh * SEQ * 16;

            float4 acc = make_float4(0.f, 0.f, 0.f, 0.f);
            float  k2 = 0.f, q2 = 0.f;
#pragma unroll
            for (int j = 0; j < 4; j++) {
                int r = R0 + rg + j * 16;
                float  k = __ldg(Kbh + r);
                float4 v = __ldcs(V4 + (size_t)r * 16 + eg);   // read-once: evict-first
                acc.x += k * v.x; acc.y += k * v.y;
                acc.z += k * v.z; acc.w += k * v.w;
                if (eg == 0) { float q = __ldg(Qbh + r); k2 += k * k; q2 += q * q; }
            }
            // lanes l and l+16 share eg: fold rg pairs within the warp
            acc.x += __shfl_down_sync(0xffffffffu, acc.x, 16);
            acc.y += __shfl_down_sync(0xffffffffu, acc.y, 16);
            acc.z += __shfl_down_sync(0xffffffffu, acc.z, 16);
            acc.w += __shfl_down_sync(0xffffffffu, acc.w, 16);
            k2    += __shfl_down_sync(0xffffffffu, k2, 16);
            q2    += __shfl_down_sync(0xffffffffu, q2, 16);
            if (lane < 16) sv[warp][lane] = acc;
            if (lane == 0) sn[warp] = make_float2(k2, q2);
            __syncthreads();                               // (A)

            float* pb = g_part + (size_t)(bh * RB + b) * PST;
            if (tid < 16) {
                float4 s = sv[0][tid];
#pragma unroll
                for (int w = 1; w < 8; w++) {
                    float4 t = sv[w][tid];
                    s.x += t.x; s.y += t.y; s.z += t.z; s.w += t.w;
                }
                ((float4*)pb)[tid] = s;                    // 272B stride: 16B aligned
            } else if (tid == 16) {
                float a = 0.f, c = 0.f;
#pragma unroll
                for (int w = 0; w < 8; w++) { a += sn[w].x; c += sn[w].y; }
                pb[64] = a; pb[65] = c;
            }
            __syncthreads();                               // (B)
            if (tid == 0) {
                __threadfence();
                int old = atomicAdd(&g_sync.cnt[bh], 1);
                s_flag = (old == RB - 1);
            }
            __syncthreads();                               // (C)

            if (s_flag) {                                  // last arriver finalizes bh
                if (tid < DV) {
                    float s = 0.f;
                    const float* pp = g_part + (size_t)bh * RB * PST + tid;
#pragma unroll 8
                    for (int j = 0; j < RB; j++) s += __ldcg(pp + (size_t)j * PST);
                    ((float*)sv)[tid] = s;
                } else if (tid == DV) {
                    float s = 0.f;
                    const float* pp = g_part + (size_t)bh * RB * PST + 64;
#pragma unroll 8
                    for (int j = 0; j < RB; j++) s += __ldcg(pp + (size_t)j * PST);
                    s_k2 = s;
                } else if (tid == DV + 1) {
                    float s = 0.f;
                    const float* pp = g_part + (size_t)bh * RB * PST + 65;
#pragma unroll 8
                    for (int j = 0; j < RB; j++) s += __ldcg(pp + (size_t)j * PST);
                    s_q2 = s;
                }
                __syncthreads();
                if (tid < DV)
                    g_coef[bh * DV + tid] = ((float*)sv)[tid] * rsqrtf(s_k2) * rsqrtf(s_q2);
                __syncthreads();
                if (tid == 0) {
                    __threadfence();
                    atomicExch(&g_sync.ready[bh], 1);
                }
            }
        }
    }

    // ------------------------------------------------------------------
    // Phase B (everyone): steal 256-row output tiles, increasing-bh order.
    // out[bh, s, e] = Q[bh, s] * coef[bh, e]
    // ------------------------------------------------------------------
    for (;;) {
        if (tid == 0) s_tile = atomicAdd(&g_sync.tile, 1);
        __syncthreads();
        int t = s_tile;
        if (t >= NTILES) break;
        int bh = t >> 6;
        int s0 = (t & 63) * TILE_ROWS;
        if (tid == 0) {
            while (*((volatile int*)&g_sync.ready[bh]) == 0) __nanosleep(256);
        }
        __syncthreads();   // releases spin AND protects s_tile reuse

        float4 c = __ldcg((const float4*)(g_coef + bh * DV) + eg);
        const float* __restrict__ Qp = Q + (size_t)bh * SEQ + s0;
        float4* __restrict__ Op = (float4*)(out + ((size_t)bh * SEQ + s0) * DV);
#pragma unroll 8
        for (int r = rg; r < TILE_ROWS; r += 16) {
            float q = __ldg(Qp + r);
            __stcs(Op + (size_t)r * 16 + eg,
                   make_float4(q * c.x, q * c.y, q * c.z, q * c.w));
        }
    }
}

extern "C" void kernel_launch(void* const* d_in, const int* in_sizes, int n_in,
                              void* d_out, int out_size)
{
    const float* Q = (const float*)d_in[0];
    const float* K = (const float*)d_in[1];
    const float* V = (const float*)d_in[2];
    float* out = (float*)d_out;

    void* sp = nullptr;
    cudaGetSymbolAddress(&sp, g_sync);
    cudaMemsetAsync(sp, 0, sizeof(SyncState), 0);   // reset cnt/ready/tile each launch

    fused_kernel<<<NBLK, 256>>>(Q, K, V, out);
}

// round 13
// speedup vs baseline: 7.7003x; 7.7003x over previous
#include <cuda_runtime.h>

#define BH        64
#define SEQ       16384
#define DV        64
#define RB        256                       // reducer blocks (bids 0..RB-1)
#define NBLK      888                       // single wave at 6 CTAs/SM on 148 SMs
#define PST       68                        // partial stride floats (272B, 16B aligned)
#define TILE_ROWS 256
#define NTILES    (BH * (SEQ / TILE_ROWS))  // 4096

struct SyncState { int cnt[BH]; int fin[BH]; int ready[BH]; int tile; };
__device__ SyncState g_sync;
__device__ __align__(16) float g_part[BH * RB * PST];
__device__ __align__(16) float g_coef[BH * DV];

__global__ void __launch_bounds__(256, 6) fused_kernel(
    const float* __restrict__ Q,
    const float* __restrict__ K,
    const float* __restrict__ V,
    float* __restrict__ out)
{
    const int b    = blockIdx.x;
    const int tid  = threadIdx.x;
    const int eg   = tid & 15;
    const int rg   = tid >> 4;
    const int lane = tid & 31;
    const int warp = tid >> 5;

    __shared__ float4 sv[2][8][16];
    __shared__ float2 sn[2][8];
    __shared__ float  red[DV][4];
    __shared__ float  rnorm[8];
    __shared__ int    s_tile, s_fin;

    // ------------------------------------------------------------------
    // Reducers (b < RB): stream 64 rows of every bh, bh PAIRS per iter.
    // Never wait on anyone; fire-and-forget cnt atomics.
    // ------------------------------------------------------------------
    if (b < RB) {
        const int R0 = b * 64;
        for (int bh = 0; bh < BH; bh += 2) {
            const float*  K0 = K + (size_t)bh * SEQ;
            const float*  Q0 = Q + (size_t)bh * SEQ;
            const float4* V0 = (const float4*)V + (size_t)bh * SEQ * 16;
            const float*  K1 = K0 + SEQ;
            const float*  Q1 = Q0 + SEQ;
            const float4* V1 = V0 + (size_t)SEQ * 16;

            float4 a0 = make_float4(0.f,0.f,0.f,0.f);
            float4 a1 = make_float4(0.f,0.f,0.f,0.f);
            float k2a=0.f,q2a=0.f,k2b=0.f,q2b=0.f;
#pragma unroll
            for (int j = 0; j < 4; j++) {
                int r = R0 + rg + j * 16;
                float  k0 = __ldg(K0 + r);
                float4 v0 = __ldcs(V0 + (size_t)r * 16 + eg);
                float  k1 = __ldg(K1 + r);
                float4 v1 = __ldcs(V1 + (size_t)r * 16 + eg);
                a0.x += k0*v0.x; a0.y += k0*v0.y; a0.z += k0*v0.z; a0.w += k0*v0.w;
                a1.x += k1*v1.x; a1.y += k1*v1.y; a1.z += k1*v1.z; a1.w += k1*v1.w;
                if (eg == 0) {
                    float qa = __ldg(Q0 + r), qb = __ldg(Q1 + r);
                    k2a += k0*k0; q2a += qa*qa;
                    k2b += k1*k1; q2b += qb*qb;
                }
            }
            a0.x += __shfl_down_sync(0xffffffffu, a0.x, 16);
            a0.y += __shfl_down_sync(0xffffffffu, a0.y, 16);
            a0.z += __shfl_down_sync(0xffffffffu, a0.z, 16);
            a0.w += __shfl_down_sync(0xffffffffu, a0.w, 16);
            a1.x += __shfl_down_sync(0xffffffffu, a1.x, 16);
            a1.y += __shfl_down_sync(0xffffffffu, a1.y, 16);
            a1.z += __shfl_down_sync(0xffffffffu, a1.z, 16);
            a1.w += __shfl_down_sync(0xffffffffu, a1.w, 16);
            k2a += __shfl_down_sync(0xffffffffu, k2a, 16);
            q2a += __shfl_down_sync(0xffffffffu, q2a, 16);
            k2b += __shfl_down_sync(0xffffffffu, k2b, 16);
            q2b += __shfl_down_sync(0xffffffffu, q2b, 16);
            if (lane < 16) { sv[0][warp][lane] = a0; sv[1][warp][lane] = a1; }
            if (lane == 0) { sn[0][warp] = make_float2(k2a,q2a);
                             sn[1][warp] = make_float2(k2b,q2b); }
            __syncthreads();

            float* pb0 = g_part + (size_t)((bh    )*RB + b) * PST;
            float* pb1 = g_part + (size_t)((bh + 1)*RB + b) * PST;
            if (tid < 16) {
                float4 s = sv[0][0][tid];
#pragma unroll
                for (int w = 1; w < 8; w++) { float4 t = sv[0][w][tid];
                    s.x+=t.x; s.y+=t.y; s.z+=t.z; s.w+=t.w; }
                ((float4*)pb0)[tid] = s;
            } else if (tid == 16) {
                float a=0.f,c=0.f;
#pragma unroll
                for (int w = 0; w < 8; w++) { a += sn[0][w].x; c += sn[0][w].y; }
                pb0[64]=a; pb0[65]=c;
            } else if (tid >= 32 && tid < 48) {
                float4 s = sv[1][0][tid-32];
#pragma unroll
                for (int w = 1; w < 8; w++) { float4 t = sv[1][w][tid-32];
                    s.x+=t.x; s.y+=t.y; s.z+=t.z; s.w+=t.w; }
                ((float4*)pb1)[tid-32] = s;
            } else if (tid == 48) {
                float a=0.f,c=0.f;
#pragma unroll
                for (int w = 0; w < 8; w++) { a += sn[1][w].x; c += sn[1][w].y; }
                pb1[64]=a; pb1[65]=c;
            }
            __syncthreads();
            if (tid == 0) {
                __threadfence();
                atomicAdd(&g_sync.cnt[bh], 1);
                atomicAdd(&g_sync.cnt[bh+1], 1);
            }
            // next iteration's post-load __syncthreads protects sv/sn reuse
        }
    }

    // ------------------------------------------------------------------
    // Writers (everyone): steal 256-row tiles in increasing-bh order.
    // First writer to want a completed-but-unfinalized bh finalizes it
    // (parallel 256-thread gather, off the reducer critical path).
    // ------------------------------------------------------------------
    for (;;) {
        if (tid == 0) s_tile = atomicAdd(&g_sync.tile, 1);
        __syncthreads();
        const int t = s_tile;
        if (t >= NTILES) break;
        const int bh = t >> 6;
        const int s0 = (t & 63) * TILE_ROWS;

        if (tid == 0) {
            s_fin = 0;
            if (*(volatile int*)&g_sync.ready[bh] == 0) {
                for (;;) {
                    if (*(volatile int*)&g_sync.ready[bh]) break;
                    if (*(volatile int*)&g_sync.cnt[bh] == RB &&
                        atomicCAS(&g_sync.fin[bh], 0, 1) == 0) { s_fin = 1; break; }
                    __nanosleep(128);
                }
            }
        }
        __syncthreads();

        if (s_fin) {
            const float* pb = g_part + (size_t)bh * RB * PST;
            {   // ktv gather: 4 threads per column e, 64-long chains, MLP 8
                int e = tid >> 2, q = tid & 3;
                float s = 0.f;
                const float* pp = pb + (size_t)(q * 64) * PST + e;
#pragma unroll 8
                for (int j = 0; j < 64; j++) s += __ldcg(pp + (size_t)j * PST);
                red[e][q] = s;
            }
            if (tid < 8) {   // norms: tid0-3 k2 quarters, tid4-7 q2 quarters
                int idx = 64 + (tid >> 2);
                int q = tid & 3;
                float s = 0.f;
                const float* pp = pb + (size_t)(q * 64) * PST + idx;
#pragma unroll 8
                for (int j = 0; j < 64; j++) s += __ldcg(pp + (size_t)j * PST);
                rnorm[tid] = s;
            }
            __syncthreads();
            if (tid < DV) {
                float kt = red[tid][0] + red[tid][1] + red[tid][2] + red[tid][3];
                float k2 = rnorm[0] + rnorm[1] + rnorm[2] + rnorm[3];
                float q2 = rnorm[4] + rnorm[5] + rnorm[6] + rnorm[7];
                g_coef[bh * DV + tid] = kt * rsqrtf(k2) * rsqrtf(q2);
            }
            __syncthreads();
            if (tid == 0) {
                __threadfence();
                atomicExch(&g_sync.ready[bh], 1);
            }
        }
        __syncthreads();   // protects s_fin/s_tile/smem reuse across loop iters

        const float4 c = __ldcg((const float4*)(g_coef + bh * DV) + eg);
        const float* __restrict__ Qp = Q + (size_t)bh * SEQ + s0;
        float4* __restrict__ Op = (float4*)(out + ((size_t)bh * SEQ + s0) * DV);
#pragma unroll 8
        for (int r = rg; r < TILE_ROWS; r += 16) {
            float q = __ldg(Qp + r);
            __stcs(Op + (size_t)r * 16 + eg,
                   make_float4(q * c.x, q * c.y, q * c.z, q * c.w));
        }
    }
}

extern "C" void kernel_launch(void* const* d_in, const int* in_sizes, int n_in,
                              void* d_out, int out_size)
{
    const float* Q = (const float*)d_in[0];
    const float* K = (const float*)d_in[1];
    const float* V = (const float*)d_in[2];
    float* out = (float*)d_out;

    void* sp = nullptr;
    cudaGetSymbolAddress(&sp, g_sync);
    cudaMemsetAsync(sp, 0, sizeof(SyncState), 0);   // reset cnt/fin/ready/tile

    fused_kernel<<<NBLK, 256>>>(Q, K, V, out);
}

// round 16
// speedup vs baseline: 12.4158x; 1.6124x over previous
#include <cuda_runtime.h>

#define BH      64
#define SEQ     16384
#define DV      64
#define NSPLIT  16
#define SCHUNK  (SEQ / NSPLIT)   // 1024
#define PSTRIDE 80               // 320 B, 16B-aligned
#define WNBLK   1184             // persistent writer blocks
#define TROWS   256
#define NTILES  (BH * (SEQ / TROWS))  // 4096

__device__ __align__(16) float g_part[BH * NSPLIT * PSTRIDE];

// ---------------------------------------------------------------------------
// Pass 1: identical to the measured-good R5 reducer (6.18 TB/s).
// ---------------------------------------------------------------------------
__global__ __launch_bounds__(256) void ktv_reduce_kernel(
    const float* __restrict__ Q,
    const float* __restrict__ K,
    const float* __restrict__ V)
{
    const int bh    = blockIdx.x;
    const int split = blockIdx.y;
    const int tid   = threadIdx.x;
    const int eg    = tid & 15;
    const int rg    = tid >> 4;

    const float* __restrict__ Kp = K + (size_t)bh * SEQ + (size_t)split * SCHUNK;
    const float* __restrict__ Qp = Q + (size_t)bh * SEQ + (size_t)split * SCHUNK;
    const float4* __restrict__ Vp =
        (const float4*)(V + (size_t)bh * SEQ * DV + (size_t)split * SCHUNK * DV);

    float4 acc = make_float4(0.f, 0.f, 0.f, 0.f);
#pragma unroll 8
    for (int s = rg; s < SCHUNK; s += 16) {
        float  k = __ldg(Kp + s);
        float4 v = __ldcs(Vp + (size_t)s * 16 + eg);
        acc.x += k * v.x; acc.y += k * v.y;
        acc.z += k * v.z; acc.w += k * v.w;
    }

    float k2 = 0.f, q2 = 0.f;
#pragma unroll 4
    for (int s = tid; s < SCHUNK; s += 256) {
        float k = __ldg(Kp + s);
        float q = __ldg(Qp + s);
        k2 += k * k;
        q2 += q * q;
    }

    __shared__ float4 sacc[256];
    __shared__ float2 skq[256];
    sacc[tid] = acc;
    skq[tid]  = make_float2(k2, q2);
    __syncthreads();

#pragma unroll
    for (int stride = 128; stride >= 16; stride >>= 1) {
        if (tid < stride) {
            float4 a = sacc[tid], b = sacc[tid + stride];
            a.x += b.x; a.y += b.y; a.z += b.z; a.w += b.w;
            sacc[tid] = a;
            float2 p = skq[tid], q = skq[tid + stride];
            p.x += q.x; p.y += q.y;
            skq[tid] = p;
        }
        __syncthreads();
    }
    if (tid < 16) {
        float2 p = skq[tid];
#pragma unroll
        for (int stride = 8; stride >= 1; stride >>= 1) {
            p.x += __shfl_down_sync(0xFFFF, p.x, stride, 16);
            p.y += __shfl_down_sync(0xFFFF, p.y, stride, 16);
        }
        float* base = g_part + (size_t)(bh * NSPLIT + split) * PSTRIDE;
        ((float4*)base)[tid] = sacc[tid];
        if (tid == 0) { base[64] = p.x; base[65] = p.y; }
    }
}

// ---------------------------------------------------------------------------
// Pass 2: persistent strided writer with PDL. Each block handles tiles
// b, b+WNBLK, ... (3-4 tiles). Per tile: recompute coef (L2-resident, cheap),
// then stream 256 rows of output with evict-first stores.
// ---------------------------------------------------------------------------
__global__ __launch_bounds__(256) void out_kernel(
    const float* __restrict__ Q,
    float* __restrict__ out)
{
    // Blocks may be dispatched while the reducer drains; wait for its
    // completion (and memory visibility) before touching g_part.
    cudaGridDependencySynchronize();

    const int tid = threadIdx.x;
    const int eg  = tid & 15;
    const int rg  = tid >> 4;

    __shared__ float scoef[DV];

    for (int t = blockIdx.x; t < NTILES; t += WNBLK) {
        const int bh = t >> 6;
        const int s0 = (t & 63) * TROWS;

        if (tid < DV) {
            float ktv = 0.f, k2 = 0.f, q2 = 0.f;
#pragma unroll
            for (int sp = 0; sp < NSPLIT; sp++) {
                const float* p = g_part + (size_t)(bh * NSPLIT + sp) * PSTRIDE;
                ktv += __ldg(p + tid);
                k2  += __ldg(p + 64);
                q2  += __ldg(p + 65);
            }
            scoef[tid] = ktv * rsqrtf(k2) * rsqrtf(q2);
        }
        __syncthreads();

        const float4 c = ((const float4*)scoef)[eg];
        const float* __restrict__ Qp = Q + (size_t)bh * SEQ + s0;
        float4* __restrict__ Op =
            (float4*)(out + ((size_t)bh * SEQ + s0) * DV);

#pragma unroll 8
        for (int r = rg; r < TROWS; r += 16) {
            float q = __ldg(Qp + r);
            __stcs(Op + (size_t)r * 16 + eg,
                   make_float4(q * c.x, q * c.y, q * c.z, q * c.w));
        }
        __syncthreads();   // protect scoef before next tile overwrites it
    }
}

extern "C" void kernel_launch(void* const* d_in, const int* in_sizes, int n_in,
                              void* d_out, int out_size)
{
    const float* Q = (const float*)d_in[0];
    const float* K = (const float*)d_in[1];
    const float* V = (const float*)d_in[2];
    float* out = (float*)d_out;

    dim3 g1(BH, NSPLIT);
    ktv_reduce_kernel<<<g1, 256>>>(Q, K, V);

    // Writer with programmatic dependent launch: blocks spin up while the
    // reducer finishes; cudaGridDependencySynchronize() gates g_part reads.
    cudaLaunchConfig_t cfg = {};
    cfg.gridDim  = dim3(WNBLK);
    cfg.blockDim = dim3(256);
    cfg.stream   = 0;
    cudaLaunchAttribute attr[1];
    attr[0].id = cudaLaunchAttributeProgrammaticStreamSerialization;
    attr[0].val.programmaticStreamSerializationAllowed = 1;
    cfg.attrs    = attr;
    cfg.numAttrs = 1;
    cudaLaunchKernelEx(&cfg, out_kernel, Q, out);
}

// round 17
// speedup vs baseline: 12.8836x; 1.0377x over previous
#include <cuda_runtime.h>

#define BH      64
#define SEQ     16384
#define DV      64
#define NSPLIT  16
#define SCHUNK  (SEQ / NSPLIT)   // 1024
#define PSTRIDE 80               // 320 B, 16B-aligned

__device__ __align__(16) float g_part[BH * NSPLIT * PSTRIDE];

// ---------------------------------------------------------------------------
// Pass 1: measured-good reducer (45.8us, 6.18 TB/s mixed read).
// ---------------------------------------------------------------------------
__global__ __launch_bounds__(256) void ktv_reduce_kernel(
    const float* __restrict__ Q,
    const float* __restrict__ K,
    const float* __restrict__ V)
{
    const int bh    = blockIdx.x;
    const int split = blockIdx.y;
    const int tid   = threadIdx.x;
    const int eg    = tid & 15;
    const int rg    = tid >> 4;

    const float* __restrict__ Kp = K + (size_t)bh * SEQ + (size_t)split * SCHUNK;
    const float* __restrict__ Qp = Q + (size_t)bh * SEQ + (size_t)split * SCHUNK;
    const float4* __restrict__ Vp =
        (const float4*)(V + (size_t)bh * SEQ * DV + (size_t)split * SCHUNK * DV);

    float4 acc = make_float4(0.f, 0.f, 0.f, 0.f);
#pragma unroll 8
    for (int s = rg; s < SCHUNK; s += 16) {
        float  k = __ldg(Kp + s);
        float4 v = __ldcs(Vp + (size_t)s * 16 + eg);
        acc.x += k * v.x; acc.y += k * v.y;
        acc.z += k * v.z; acc.w += k * v.w;
    }

    float k2 = 0.f, q2 = 0.f;
#pragma unroll 4
    for (int s = tid; s < SCHUNK; s += 256) {
        float k = __ldg(Kp + s);
        float q = __ldg(Qp + s);
        k2 += k * k;
        q2 += q * q;
    }

    __shared__ float4 sacc[256];
    __shared__ float2 skq[256];
    sacc[tid] = acc;
    skq[tid]  = make_float2(k2, q2);
    __syncthreads();

#pragma unroll
    for (int stride = 128; stride >= 16; stride >>= 1) {
        if (tid < stride) {
            float4 a = sacc[tid], b = sacc[tid + stride];
            a.x += b.x; a.y += b.y; a.z += b.z; a.w += b.w;
            sacc[tid] = a;
            float2 p = skq[tid], q = skq[tid + stride];
            p.x += q.x; p.y += q.y;
            skq[tid] = p;
        }
        __syncthreads();
    }
    if (tid < 16) {
        float2 p = skq[tid];
#pragma unroll
        for (int stride = 8; stride >= 1; stride >>= 1) {
            p.x += __shfl_down_sync(0xFFFF, p.x, stride, 16);
            p.y += __shfl_down_sync(0xFFFF, p.y, stride, 16);
        }
        float* base = g_part + (size_t)(bh * NSPLIT + split) * PSTRIDE;
        ((float4*)base)[tid] = sacc[tid];
        if (tid == 0) { base[64] = p.x; base[65] = p.y; }
    }
}

// ---------------------------------------------------------------------------
// Pass 2: EXACT R5 shape (one 256-row tile per block, grid 4096) + PDL.
// __launch_bounds__(256,8) pins regs <= 32 so occupancy stays at 8 CTAs/SM.
// ---------------------------------------------------------------------------
__global__ void __launch_bounds__(256, 8) out_kernel(
    const float* __restrict__ Q,
    float* __restrict__ out)
{
    // PDL: blocks may be dispatched before the reducer drains; gate g_part.
    cudaGridDependencySynchronize();

    const int bh  = blockIdx.y;
    const int s0  = blockIdx.x * 256;
    const int tid = threadIdx.x;
    const int eg  = tid & 15;
    const int rg  = tid >> 4;

    __shared__ float scoef[DV];
    if (tid < DV) {
        float ktv = 0.f, k2 = 0.f, q2 = 0.f;
#pragma unroll
        for (int sp = 0; sp < NSPLIT; sp++) {
            const float* p = g_part + (size_t)(bh * NSPLIT + sp) * PSTRIDE;
            ktv += __ldg(p + tid);
            k2  += __ldg(p + 64);
            q2  += __ldg(p + 65);
        }
        scoef[tid] = ktv * rsqrtf(k2) * rsqrtf(q2);
    }
    __syncthreads();

    const float4 c = ((const float4*)scoef)[eg];
    const float* __restrict__ Qp = Q + (size_t)bh * SEQ + s0;
    float4* __restrict__ Op =
        (float4*)(out + ((size_t)bh * SEQ + s0) * DV);

#pragma unroll 8
    for (int r = rg; r < 256; r += 16) {
        float q = __ldg(Qp + r);
        __stcs(Op + (size_t)r * 16 + eg,
               make_float4(q * c.x, q * c.y, q * c.z, q * c.w));
    }
}

extern "C" void kernel_launch(void* const* d_in, const int* in_sizes, int n_in,
                              void* d_out, int out_size)
{
    const float* Q = (const float*)d_in[0];
    const float* K = (const float*)d_in[1];
    const float* V = (const float*)d_in[2];
    float* out = (float*)d_out;

    dim3 g1(BH, NSPLIT);
    ktv_reduce_kernel<<<g1, 256>>>(Q, K, V);

    cudaLaunchConfig_t cfg = {};
    cfg.gridDim  = dim3(SEQ / 256, BH);   // 64 x 64 = 4096 blocks, R5 shape
    cfg.blockDim = dim3(256);
    cfg.stream   = 0;
    cudaLaunchAttribute attr[1];
    attr[0].id = cudaLaunchAttributeProgrammaticStreamSerialization;
    attr[0].val.programmaticStreamSerializationAllowed = 1;
    cfg.attrs    = attr;
    cfg.numAttrs = 1;
    cudaLaunchKernelEx(&cfg, out_kernel, Q, out);
}